// round 7
// baseline (speedup 1.0000x reference)
#include <cuda_runtime.h>
#include <cstdint>

#define QPB 16   // queries per block: 8 warps x 2 half-warp queries

// Per-lane weight-block stride (words): 16B aligned and % 8 == 4 so the
// 8-lane LDS.128 phases tile all 32 banks conflict-free.
template <int P> struct WStride { static constexpr int v = ((4 * 3 * P) % 8 == 4) ? (4 * 3 * P) : (4 * 3 * P + 4); };
template <> struct WStride<1> { static constexpr int v = 20; };

// Partial-sum scratch layout: per query region of PREG=240 words (240 % 32 == 16,
// so the two half-warps of a warp land on disjoint bank halves). Within a region,
// column j occupies words [j*20, j*20+16) (stride 20: 16B-aligned, odd multiple of 4).
#define PREG 240

// Fill per-lane weight blocks: sWb[(k>>2)*STRIDE + c*4 + (k&3)] = W[k][c]
// where W cols 0..2P-1 = w_est, 2P..3P-1 = w_wt. sB[c] = bias.
__device__ __forceinline__ void load_wb(float* sWb, float* sB, int STRIDE,
    const float* __restrict__ we, const float* __restrict__ be,
    const float* __restrict__ ww, const float* __restrict__ bw,
    int P, int tid, int nthreads)
{
    const int NCOL = 3 * P;
    for (int i = tid; i < 64 * NCOL; i += nthreads) {
        int k = i / NCOL, c = i % NCOL;
        float v = (c < 2 * P) ? we[k * (2 * P) + c] : ww[k * P + (c - 2 * P)];
        sWb[(k >> 2) * STRIDE + c * 4 + (k & 3)] = v;
    }
    if (tid < NCOL) sB[tid] = (tid < 2 * P) ? be[tid] : bw[tid - 2 * P];
}

// One stage for one query on a 16-lane half-warp; lane owns 4 channels (c4).
// Returns new feature c4; updates spx/spy (identical in all lanes).
template <int P>
__device__ __forceinline__ float4 run_stage(
    float4 c4, int sl, int qw,
    const float* __restrict__ sWb,   // lane blocks, stride WStride<P>::v
    const float* __restrict__ sB,
    float* __restrict__ sPart,       // [QPB * PREG] transpose-reduce scratch
    float* __restrict__ sLog,        // [QPB * 16] logit broadcast
    float& spx, float& spy,
    float base_x, float base_y, float sc_x, float sc_y,
    int h, int w,
    const float* __restrict__ vbase, bool active)
{
    constexpr int NCOL = 3 * P;
    constexpr int STRIDE = WStride<P>::v;

    // ---- register GEMM partials: p[j] = c4 . W[4sl..4sl+3][j] -> scratch ----
    const float4* blk = reinterpret_cast<const float4*>(sWb + sl * STRIDE);
    float* myPart = sPart + qw * PREG;
    #pragma unroll
    for (int j = 0; j < NCOL; j++) {
        const float4 wv = blk[j];
        myPart[j * 20 + sl] =
            fmaf(c4.x, wv.x, fmaf(c4.y, wv.y, fmaf(c4.z, wv.z, c4.w * wv.w)));
    }
    __syncwarp();

    // ---- column owners sum 16 partials (4x LDS.128), add bias, publish ----
    if (sl < NCOL) {
        const float4* col = reinterpret_cast<const float4*>(myPart + sl * 20);
        const float4 a = col[0], b = col[1], c = col[2], d = col[3];
        const float s = (((a.x + a.y) + (a.z + a.w)) + ((b.x + b.y) + (b.z + b.w)))
                      + (((c.x + c.y) + (c.z + c.w)) + ((d.x + d.y) + (d.z + d.w)));
        sLog[qw * 16 + sl] = s + sB[sl];
    }
    __syncwarp();

    // ---- broadcast logits to all lanes ----
    float lg[NCOL];
    {
        const float4* lq = reinterpret_cast<const float4*>(sLog + qw * 16);
        #pragma unroll
        for (int v4 = 0; v4 < (NCOL + 3) / 4; v4++) {
            const float4 t = lq[v4];
            if (4 * v4 + 0 < NCOL) lg[4 * v4 + 0] = t.x;
            if (4 * v4 + 1 < NCOL) lg[4 * v4 + 1] = t.y;
            if (4 * v4 + 2 < NCOL) lg[4 * v4 + 2] = t.z;
            if (4 * v4 + 3 < NCOL) lg[4 * v4 + 3] = t.w;
        }
    }

    // ---- softmax + argmax over P ----
    float wl[P];
    float m = -1e30f; int mid = 0;
    #pragma unroll
    for (int p = 0; p < P; p++) {
        wl[p] = lg[2 * P + p];
        if (wl[p] > m) { m = wl[p]; mid = p; }   // strict > => first max (jnp.argmax)
    }
    float sum = 0.f;
    #pragma unroll
    for (int p = 0; p < P; p++) { wl[p] = expf(wl[p] - m); sum += wl[p]; }
    const float inv = 1.0f / sum;

    // offsets use OLD speed; speed updated with delta[argmax]
    const float bx = fmaf(spx, sc_x, base_x);
    const float by = fmaf(spy, sc_y, base_y);
    spx += lg[2 * mid];
    spy += lg[2 * mid + 1];

    float4 acc = make_float4(0.f, 0.f, 0.f, 0.f);
    #pragma unroll
    for (int p = 0; p < P; p++) {
        const float x = fmaf(lg[2 * p],     sc_x, bx);
        const float y = fmaf(lg[2 * p + 1], sc_y, by);
        const float x0f = floorf(x), y0f = floorf(y);
        const float fx = x - x0f, fy = y - y0f;
        const int x0 = (int)x0f, y0 = (int)y0f;

        float4 s = make_float4(0.f, 0.f, 0.f, 0.f);
        #pragma unroll
        for (int cy = 0; cy < 2; cy++) {
            #pragma unroll
            for (int cx = 0; cx < 2; cx++) {
                const int xi = x0 + cx, yi = y0 + cy;
                const bool valid = active & (xi >= 0) & (xi < w) & (yi >= 0) & (yi < h);
                const float cw = (cx ? fx : (1.f - fx)) * (cy ? fy : (1.f - fy));
                if (valid) {
                    const float4 v = *reinterpret_cast<const float4*>(
                        vbase + ((size_t)yi * w + xi) * 64);
                    s.x += v.x * cw; s.y += v.y * cw;
                    s.z += v.z * cw; s.w += v.w * cw;
                }
            }
        }
        const float wp = wl[p] * inv;
        acc.x += s.x * wp; acc.y += s.y * wp;
        acc.z += s.z * wp; acc.w += s.w * wp;
    }
    return acc;
}

template <int P1, int P2, int P3>
__global__ __launch_bounds__(256) void speed_sampler_fused(
    const float* __restrict__ curIn,    // [BFN, 64]
    const float* __restrict__ indices,  // [BFN, 2]
    const float* __restrict__ value,    // [BF*HW, 64]
    const float* __restrict__ we1, const float* __restrict__ be1,
    const float* __restrict__ ww1, const float* __restrict__ bw1,
    const float* __restrict__ we2, const float* __restrict__ be2,
    const float* __restrict__ ww2, const float* __restrict__ bw2,
    const float* __restrict__ we3, const float* __restrict__ be3,
    const float* __restrict__ ww3, const float* __restrict__ bw3,
    const int* __restrict__ hsp_p, const int* __restrict__ wsp_p,
    float* __restrict__ out,            // [BFN, 66]
    int BFN, int BFHW)
{
    constexpr int S1 = WStride<P1>::v, S2 = WStride<P2>::v, S3 = WStride<P3>::v;
    __shared__ __align__(16) float sWb1[16 * S1];
    __shared__ __align__(16) float sWb2[16 * S2];
    __shared__ __align__(16) float sWb3[16 * S3];
    __shared__ float sB1[3 * P1], sB2[3 * P2], sB3[3 * P3];
    __shared__ __align__(16) float sPart[QPB * PREG];
    __shared__ __align__(16) float sLog[QPB * 16];

    const int tid = threadIdx.x;
    load_wb(sWb1, sB1, S1, we1, be1, ww1, bw1, P1, tid, blockDim.x);
    load_wb(sWb2, sB2, S2, we2, be2, ww2, bw2, P2, tid, blockDim.x);
    load_wb(sWb3, sB3, S3, we3, be3, ww3, bw3, P3, tid, blockDim.x);

    const int sl = tid & 15;            // sub-lane within half-warp
    const int qw = tid >> 4;            // query slot in block, 0..15
    const int q = blockIdx.x * QPB + qw;
    const int h = *hsp_p, w = *wsp_p;
    const int HW = h * w;
    const int BF = BFHW / HW;
    const int Nq = BFN / BF;
    const bool active = q < BFN;

    __syncthreads();

    // x = (idx0 + 0.1*off_x) * (w/h) - 0.5 ; y = (idx1 + 0.1*off_y) * (h/w) - 0.5
    const float fh = (float)h, fw = (float)w;
    const float rwh = fw / fh, rhw = fh / fw;
    const float sc_x = 0.1f * rwh, sc_y = 0.1f * rhw;

    float4 c4 = make_float4(0.f, 0.f, 0.f, 0.f);
    float base_x = 0.f, base_y = 0.f;
    const float* vbase = value;
    if (active) {
        c4 = *reinterpret_cast<const float4*>(curIn + (size_t)q * 64 + 4 * sl);
        const float idx0 = indices[(size_t)q * 2];
        const float idx1 = indices[(size_t)q * 2 + 1];
        base_x = fmaf(idx0, rwh, -0.5f);
        base_y = fmaf(idx1, rhw, -0.5f);
        const int bf = q / Nq;
        vbase = value + (size_t)bf * HW * 64 + 4 * sl;
    }
    float spx = 0.f, spy = 0.f;

    c4 = run_stage<P1>(c4, sl, qw, sWb1, sB1, sPart, sLog, spx, spy, base_x, base_y, sc_x, sc_y, h, w, vbase, active);
    c4 = run_stage<P2>(c4, sl, qw, sWb2, sB2, sPart, sLog, spx, spy, base_x, base_y, sc_x, sc_y, h, w, vbase, active);
    c4 = run_stage<P3>(c4, sl, qw, sWb3, sB3, sPart, sLog, spx, spy, base_x, base_y, sc_x, sc_y, h, w, vbase, active);

    if (active) {
        // out row = 66 floats: 64 features + 2 speed. (q*66 + 4*sl) is even -> 8B aligned.
        float* o = out + (size_t)q * 66 + 4 * sl;
        *reinterpret_cast<float2*>(o)     = make_float2(c4.x, c4.y);
        *reinterpret_cast<float2*>(o + 2) = make_float2(c4.z, c4.w);
        if (sl == 0) {
            out[(size_t)q * 66 + 64] = spx;
            out[(size_t)q * 66 + 65] = spy;
        }
    }
}

extern "C" void kernel_launch(void* const* d_in, const int* in_sizes, int n_in,
                              void* d_out, int out_size)
{
    // 0: cur_features_dense [BF,N,C]   1: cur_indices_dense [BF,N,2]
    // 2: pre_value [BF,HW,1,C]         3: h_sp (int)   4: w_sp (int)
    // 5..8:  w_est1,b_est1,w_wt1,b_wt1
    // 9..12: w_est2,b_est2,w_wt2,b_wt2
    // 13..16:w_est3,b_est3,w_wt3,b_wt3
    const float* cur  = (const float*)d_in[0];
    const float* idxs = (const float*)d_in[1];
    const float* val  = (const float*)d_in[2];
    const int*   hsp  = (const int*)d_in[3];
    const int*   wsp  = (const int*)d_in[4];

    const int P1 = in_sizes[6] / 2;
    const int P2 = in_sizes[10] / 2;
    const int P3 = in_sizes[14] / 2;
    const int C  = in_sizes[5] / in_sizes[6];
    const int BFN  = in_sizes[0] / C;
    const int BFHW = in_sizes[2] / C;

    float* out = (float*)d_out;
    dim3 block(256);
    dim3 grid((BFN + QPB - 1) / QPB);

    if (P1 == 4 && P2 == 2 && P3 == 1) {
        speed_sampler_fused<4, 2, 1><<<grid, block>>>(
            cur, idxs, val,
            (const float*)d_in[5],  (const float*)d_in[6],
            (const float*)d_in[7],  (const float*)d_in[8],
            (const float*)d_in[9],  (const float*)d_in[10],
            (const float*)d_in[11], (const float*)d_in[12],
            (const float*)d_in[13], (const float*)d_in[14],
            (const float*)d_in[15], (const float*)d_in[16],
            hsp, wsp, out, BFN, BFHW);
    }
}

// round 8
// speedup vs baseline: 1.0087x; 1.0087x over previous
#include <cuda_runtime.h>
#include <cstdint>

#define QPB 16   // queries per block: 8 warps x 2 half-warp queries

// Per-lane weight-block stride (words): 16B aligned and % 8 == 4 so the
// 8-lane LDS.128 phases tile all 32 banks conflict-free.
template <int P> struct WStride { static constexpr int v = ((4 * 3 * P) % 8 == 4) ? (4 * 3 * P) : (4 * 3 * P + 4); };
template <> struct WStride<1> { static constexpr int v = 20; };

// Partial-sum scratch: per query region of PREG=240 words (240 % 32 == 16 so the
// two half-warps of a warp land on disjoint bank halves). Column j at [j*20, j*20+16).
#define PREG 240

__device__ __forceinline__ void load_wb(float* sWb, float* sB, int STRIDE,
    const float* __restrict__ we, const float* __restrict__ be,
    const float* __restrict__ ww, const float* __restrict__ bw,
    int P, int tid, int nthreads)
{
    const int NCOL = 3 * P;
    for (int i = tid; i < 64 * NCOL; i += nthreads) {
        int k = i / NCOL, c = i % NCOL;
        float v = (c < 2 * P) ? we[k * (2 * P) + c] : ww[k * P + (c - 2 * P)];
        sWb[(k >> 2) * STRIDE + c * 4 + (k & 3)] = v;
    }
    if (tid < NCOL) sB[tid] = (tid < 2 * P) ? be[tid] : bw[tid - 2 * P];
}

// One stage for one query on a 16-lane half-warp; lane owns 4 channels (c4).
template <int P>
__device__ __forceinline__ float4 run_stage(
    float4 c4, int sl, int qw,
    const float* __restrict__ sWb,
    const float* __restrict__ sB,
    float* __restrict__ sPart,
    float* __restrict__ sLog,
    float& spx, float& spy,
    float base_x, float base_y, float sc_x, float sc_y,
    int h, int w,
    const float* __restrict__ vbase, bool active)
{
    constexpr int NCOL = 3 * P;
    constexpr int STRIDE = WStride<P>::v;

    // ---- register GEMM partials -> transpose-reduce scratch ----
    const float4* blk = reinterpret_cast<const float4*>(sWb + sl * STRIDE);
    float* myPart = sPart + qw * PREG;
    #pragma unroll
    for (int j = 0; j < NCOL; j++) {
        const float4 wv = blk[j];
        myPart[j * 20 + sl] =
            fmaf(c4.x, wv.x, fmaf(c4.y, wv.y, fmaf(c4.z, wv.z, c4.w * wv.w)));
    }
    __syncwarp();

    if (sl < NCOL) {
        const float4* col = reinterpret_cast<const float4*>(myPart + sl * 20);
        const float4 a = col[0], b = col[1], c = col[2], d = col[3];
        const float s = (((a.x + a.y) + (a.z + a.w)) + ((b.x + b.y) + (b.z + b.w)))
                      + (((c.x + c.y) + (c.z + c.w)) + ((d.x + d.y) + (d.z + d.w)));
        sLog[qw * 16 + sl] = s + sB[sl];
    }
    __syncwarp();

    float lg[NCOL];
    {
        const float4* lq = reinterpret_cast<const float4*>(sLog + qw * 16);
        #pragma unroll
        for (int v4 = 0; v4 < (NCOL + 3) / 4; v4++) {
            const float4 t = lq[v4];
            if (4 * v4 + 0 < NCOL) lg[4 * v4 + 0] = t.x;
            if (4 * v4 + 1 < NCOL) lg[4 * v4 + 1] = t.y;
            if (4 * v4 + 2 < NCOL) lg[4 * v4 + 2] = t.z;
            if (4 * v4 + 3 < NCOL) lg[4 * v4 + 3] = t.w;
        }
    }

    // ---- softmax + argmax over P ----
    float wl[P];
    float m = -1e30f; int mid = 0;
    #pragma unroll
    for (int p = 0; p < P; p++) {
        wl[p] = lg[2 * P + p];
        if (wl[p] > m) { m = wl[p]; mid = p; }   // strict > => first max (jnp.argmax)
    }
    float sum = 0.f;
    #pragma unroll
    for (int p = 0; p < P; p++) { wl[p] = expf(wl[p] - m); sum += wl[p]; }
    const float inv = 1.0f / sum;

    // offsets use OLD speed; speed updated with delta[argmax]
    const float bx = fmaf(spx, sc_x, base_x);
    const float by = fmaf(spy, sc_y, base_y);
    spx += lg[2 * mid];
    spy += lg[2 * mid + 1];

    float4 acc = make_float4(0.f, 0.f, 0.f, 0.f);
    #pragma unroll
    for (int p = 0; p < P; p++) {
        const float x = fmaf(lg[2 * p],     sc_x, bx);
        const float y = fmaf(lg[2 * p + 1], sc_y, by);
        const float x0f = floorf(x), y0f = floorf(y);
        const float fx = x - x0f, fy = y - y0f;
        const int x0 = (int)x0f, y0 = (int)y0f;
        const int x1 = x0 + 1,   y1 = y0 + 1;

        const float wp = active ? wl[p] * inv : 0.f;
        // fold validity into axis weights; clamp indices (reference clips too)
        const float wx0 = (x0 >= 0) ? (1.f - fx) : 0.f;          // x0 < w guaranteed unless x1 also oob; handle both:
        const float wx1 = (x1 < w)  ? fx         : 0.f;
        const float wx0c = (x0 < w) ? wx0 : 0.f;
        const float wx1c = (x1 >= 0) ? wx1 : 0.f;
        const float wy0 = ((y0 >= 0) & (y0 < h)) ? (1.f - fy) * wp : 0.f;
        const float wy1 = ((y1 >= 0) & (y1 < h)) ? fy * wp         : 0.f;

        const int xc0 = min(max(x0, 0), w - 1);
        const int xc1 = min(max(x1, 0), w - 1);
        const int r0 = min(max(y0, 0), h - 1) * w;
        const int r1 = min(max(y1, 0), h - 1) * w;

        // 4 unconditional vector loads (int32 offsets)
        const float4 v00 = *reinterpret_cast<const float4*>(vbase + (r0 + xc0) * 64);
        const float4 v01 = *reinterpret_cast<const float4*>(vbase + (r0 + xc1) * 64);
        const float4 v10 = *reinterpret_cast<const float4*>(vbase + (r1 + xc0) * 64);
        const float4 v11 = *reinterpret_cast<const float4*>(vbase + (r1 + xc1) * 64);

        const float c00 = wx0c * wy0, c01 = wx1c * wy0;
        const float c10 = wx0c * wy1, c11 = wx1c * wy1;

        acc.x = fmaf(v00.x, c00, acc.x); acc.y = fmaf(v00.y, c00, acc.y);
        acc.z = fmaf(v00.z, c00, acc.z); acc.w = fmaf(v00.w, c00, acc.w);
        acc.x = fmaf(v01.x, c01, acc.x); acc.y = fmaf(v01.y, c01, acc.y);
        acc.z = fmaf(v01.z, c01, acc.z); acc.w = fmaf(v01.w, c01, acc.w);
        acc.x = fmaf(v10.x, c10, acc.x); acc.y = fmaf(v10.y, c10, acc.y);
        acc.z = fmaf(v10.z, c10, acc.z); acc.w = fmaf(v10.w, c10, acc.w);
        acc.x = fmaf(v11.x, c11, acc.x); acc.y = fmaf(v11.y, c11, acc.y);
        acc.z = fmaf(v11.z, c11, acc.z); acc.w = fmaf(v11.w, c11, acc.w);
    }
    return acc;
}

template <int P1, int P2, int P3>
__global__ __launch_bounds__(256) void speed_sampler_fused(
    const float* __restrict__ curIn,
    const float* __restrict__ indices,
    const float* __restrict__ value,
    const float* __restrict__ we1, const float* __restrict__ be1,
    const float* __restrict__ ww1, const float* __restrict__ bw1,
    const float* __restrict__ we2, const float* __restrict__ be2,
    const float* __restrict__ ww2, const float* __restrict__ bw2,
    const float* __restrict__ we3, const float* __restrict__ be3,
    const float* __restrict__ ww3, const float* __restrict__ bw3,
    const int* __restrict__ hsp_p, const int* __restrict__ wsp_p,
    float* __restrict__ out,
    int BFN, int BFHW)
{
    constexpr int S1 = WStride<P1>::v, S2 = WStride<P2>::v, S3 = WStride<P3>::v;
    __shared__ __align__(16) float sWb1[16 * S1];
    __shared__ __align__(16) float sWb2[16 * S2];
    __shared__ __align__(16) float sWb3[16 * S3];
    __shared__ float sB1[3 * P1], sB2[3 * P2], sB3[3 * P3];
    __shared__ __align__(16) float sPart[QPB * PREG];
    __shared__ __align__(16) float sLog[QPB * 16];

    const int tid = threadIdx.x;
    load_wb(sWb1, sB1, S1, we1, be1, ww1, bw1, P1, tid, blockDim.x);
    load_wb(sWb2, sB2, S2, we2, be2, ww2, bw2, P2, tid, blockDim.x);
    load_wb(sWb3, sB3, S3, we3, be3, ww3, bw3, P3, tid, blockDim.x);

    const int sl = tid & 15;
    const int qw = tid >> 4;
    const int q = blockIdx.x * QPB + qw;
    const int h = *hsp_p, w = *wsp_p;
    const int HW = h * w;
    const int BF = BFHW / HW;
    const int Nq = BFN / BF;
    const bool active = q < BFN;

    __syncthreads();

    const float fh = (float)h, fw = (float)w;
    const float rwh = fw / fh, rhw = fh / fw;
    const float sc_x = 0.1f * rwh, sc_y = 0.1f * rhw;

    float4 c4 = make_float4(0.f, 0.f, 0.f, 0.f);
    float base_x = -0.5f, base_y = -0.5f;
    const float* vbase = value + 4 * sl;
    if (active) {
        c4 = *reinterpret_cast<const float4*>(curIn + (size_t)q * 64 + 4 * sl);
        const float2 idx = *reinterpret_cast<const float2*>(indices + (size_t)q * 2);
        base_x = fmaf(idx.x, rwh, -0.5f);
        base_y = fmaf(idx.y, rhw, -0.5f);
        const int bf = q / Nq;
        vbase += (size_t)bf * HW * 64;
    }
    float spx = 0.f, spy = 0.f;

    c4 = run_stage<P1>(c4, sl, qw, sWb1, sB1, sPart, sLog, spx, spy, base_x, base_y, sc_x, sc_y, h, w, vbase, active);
    c4 = run_stage<P2>(c4, sl, qw, sWb2, sB2, sPart, sLog, spx, spy, base_x, base_y, sc_x, sc_y, h, w, vbase, active);
    c4 = run_stage<P3>(c4, sl, qw, sWb3, sB3, sPart, sLog, spx, spy, base_x, base_y, sc_x, sc_y, h, w, vbase, active);

    if (active) {
        float* o = out + (size_t)q * 66 + 4 * sl;
        *reinterpret_cast<float2*>(o)     = make_float2(c4.x, c4.y);
        *reinterpret_cast<float2*>(o + 2) = make_float2(c4.z, c4.w);
        if (sl == 0) {
            out[(size_t)q * 66 + 64] = spx;
            out[(size_t)q * 66 + 65] = spy;
        }
    }
}

extern "C" void kernel_launch(void* const* d_in, const int* in_sizes, int n_in,
                              void* d_out, int out_size)
{
    const float* cur  = (const float*)d_in[0];
    const float* idxs = (const float*)d_in[1];
    const float* val  = (const float*)d_in[2];
    const int*   hsp  = (const int*)d_in[3];
    const int*   wsp  = (const int*)d_in[4];

    const int P1 = in_sizes[6] / 2;
    const int P2 = in_sizes[10] / 2;
    const int P3 = in_sizes[14] / 2;
    const int C  = in_sizes[5] / in_sizes[6];
    const int BFN  = in_sizes[0] / C;
    const int BFHW = in_sizes[2] / C;

    float* out = (float*)d_out;
    dim3 block(256);
    dim3 grid((BFN + QPB - 1) / QPB);

    if (P1 == 4 && P2 == 2 && P3 == 1) {
        speed_sampler_fused<4, 2, 1><<<grid, block>>>(
            cur, idxs, val,
            (const float*)d_in[5],  (const float*)d_in[6],
            (const float*)d_in[7],  (const float*)d_in[8],
            (const float*)d_in[9],  (const float*)d_in[10],
            (const float*)d_in[11], (const float*)d_in[12],
            (const float*)d_in[13], (const float*)d_in[14],
            (const float*)d_in[15], (const float*)d_in[16],
            hsp, wsp, out, BFN, BFHW);
    }
}

// round 9
// speedup vs baseline: 1.0749x; 1.0656x over previous
#include <cuda_runtime.h>
#include <cstdint>

#define QPB 16   // queries per block: 8 warps x 2 half-warp queries

// Per-lane weight-block stride (words): 16B aligned and % 8 == 4 so the
// 8-lane LDS.128 phases tile all 32 banks conflict-free.
template <int P> struct WStride { static constexpr int v = ((4 * 3 * P) % 8 == 4) ? (4 * 3 * P) : (4 * 3 * P + 4); };
template <> struct WStride<1> { static constexpr int v = 20; };

// Partial-sum scratch: per query region of PREG=240 words (240 % 32 == 16 so the
// two half-warps of a warp land on disjoint bank halves). Column j at [j*20, j*20+16).
#define PREG 240

// Divide-free staging: i indexes (c,k) as i = c*64 + k.
__device__ __forceinline__ void load_wb(float* sWb, float* sB, int STRIDE,
    const float* __restrict__ we, const float* __restrict__ be,
    const float* __restrict__ ww, const float* __restrict__ bw,
    int P, int tid, int nthreads)
{
    const int NCOL = 3 * P;
    for (int i = tid; i < 64 * NCOL; i += nthreads) {
        const int c = i >> 6, k = i & 63;
        float v = (c < 2 * P) ? we[k * (2 * P) + c] : ww[k * P + (c - 2 * P)];
        sWb[(k >> 2) * STRIDE + c * 4 + (k & 3)] = v;
    }
    if (tid < NCOL) sB[tid] = (tid < 2 * P) ? be[tid] : bw[tid - 2 * P];
}

// One stage for one query on a 16-lane half-warp; lane owns 4 channels (c4).
template <int P>
__device__ __forceinline__ float4 run_stage(
    float4 c4, int sl, int qw,
    const float* __restrict__ sWb,
    const float* __restrict__ sB,
    float* __restrict__ sPart,
    float* __restrict__ sLog,
    float& spx, float& spy,
    float base_x, float base_y, float sc_x, float sc_y,
    int h, int w,
    const float* __restrict__ vbase, bool active)
{
    constexpr int NCOL = 3 * P;
    constexpr int STRIDE = WStride<P>::v;

    // ---- register GEMM partials -> transpose-reduce scratch ----
    const float4* blk = reinterpret_cast<const float4*>(sWb + sl * STRIDE);
    float* myPart = sPart + qw * PREG;
    #pragma unroll
    for (int j = 0; j < NCOL; j++) {
        const float4 wv = blk[j];
        myPart[j * 20 + sl] =
            fmaf(c4.x, wv.x, fmaf(c4.y, wv.y, fmaf(c4.z, wv.z, c4.w * wv.w)));
    }
    __syncwarp();

    if (sl < NCOL) {
        const float4* col = reinterpret_cast<const float4*>(myPart + sl * 20);
        const float4 a = col[0], b = col[1], c = col[2], d = col[3];
        const float s = (((a.x + a.y) + (a.z + a.w)) + ((b.x + b.y) + (b.z + b.w)))
                      + (((c.x + c.y) + (c.z + c.w)) + ((d.x + d.y) + (d.z + d.w)));
        sLog[qw * 16 + sl] = s + sB[sl];
    }
    __syncwarp();

    float lg[NCOL];
    {
        const float4* lq = reinterpret_cast<const float4*>(sLog + qw * 16);
        #pragma unroll
        for (int v4 = 0; v4 < (NCOL + 3) / 4; v4++) {
            const float4 t = lq[v4];
            if (4 * v4 + 0 < NCOL) lg[4 * v4 + 0] = t.x;
            if (4 * v4 + 1 < NCOL) lg[4 * v4 + 1] = t.y;
            if (4 * v4 + 2 < NCOL) lg[4 * v4 + 2] = t.z;
            if (4 * v4 + 3 < NCOL) lg[4 * v4 + 3] = t.w;
        }
    }

    // ---- softmax + argmax over P ----
    float wl[P];
    float m = -1e30f; int mid = 0;
    #pragma unroll
    for (int p = 0; p < P; p++) {
        wl[p] = lg[2 * P + p];
        if (wl[p] > m) { m = wl[p]; mid = p; }   // strict > => first max (jnp.argmax)
    }
    float sum = 0.f;
    #pragma unroll
    for (int p = 0; p < P; p++) { wl[p] = expf(wl[p] - m); sum += wl[p]; }
    const float inv = 1.0f / sum;

    // offsets use OLD speed; speed updated with delta[argmax]
    const float bx = fmaf(spx, sc_x, base_x);
    const float by = fmaf(spy, sc_y, base_y);
    spx += lg[2 * mid];
    spy += lg[2 * mid + 1];

    float4 acc = make_float4(0.f, 0.f, 0.f, 0.f);
    #pragma unroll
    for (int p = 0; p < P; p++) {
        const float x = fmaf(lg[2 * p],     sc_x, bx);
        const float y = fmaf(lg[2 * p + 1], sc_y, by);
        const float x0f = floorf(x), y0f = floorf(y);
        const float fx = x - x0f, fy = y - y0f;
        const int x0 = (int)x0f, y0 = (int)y0f;
        const int x1 = x0 + 1,   y1 = y0 + 1;

        const float wp = active ? wl[p] * inv : 0.f;
        // validity folded into axis weights (unsigned compare = 1 op each)
        const float wx0 = ((unsigned)x0 < (unsigned)w) ? (1.f - fx) : 0.f;
        const float wx1 = ((unsigned)x1 < (unsigned)w) ? fx         : 0.f;
        const float wy0 = ((unsigned)y0 < (unsigned)h) ? (1.f - fy) * wp : 0.f;
        const float wy1 = ((unsigned)y1 < (unsigned)h) ? fy * wp         : 0.f;

        const int xc0 = min(max(x0, 0), w - 1);
        const int xc1 = min(max(x1, 0), w - 1);
        const int r0 = min(max(y0, 0), h - 1) * w;
        const int r1 = min(max(y1, 0), h - 1) * w;

        const float4 v00 = *reinterpret_cast<const float4*>(vbase + (r0 + xc0) * 64);
        const float4 v01 = *reinterpret_cast<const float4*>(vbase + (r0 + xc1) * 64);
        const float4 v10 = *reinterpret_cast<const float4*>(vbase + (r1 + xc0) * 64);
        const float4 v11 = *reinterpret_cast<const float4*>(vbase + (r1 + xc1) * 64);

        const float c00 = wx0 * wy0, c01 = wx1 * wy0;
        const float c10 = wx0 * wy1, c11 = wx1 * wy1;

        acc.x = fmaf(v00.x, c00, acc.x); acc.y = fmaf(v00.y, c00, acc.y);
        acc.z = fmaf(v00.z, c00, acc.z); acc.w = fmaf(v00.w, c00, acc.w);
        acc.x = fmaf(v01.x, c01, acc.x); acc.y = fmaf(v01.y, c01, acc.y);
        acc.z = fmaf(v01.z, c01, acc.z); acc.w = fmaf(v01.w, c01, acc.w);
        acc.x = fmaf(v10.x, c10, acc.x); acc.y = fmaf(v10.y, c10, acc.y);
        acc.z = fmaf(v10.z, c10, acc.z); acc.w = fmaf(v10.w, c10, acc.w);
        acc.x = fmaf(v11.x, c11, acc.x); acc.y = fmaf(v11.y, c11, acc.y);
        acc.z = fmaf(v11.z, c11, acc.z); acc.w = fmaf(v11.w, c11, acc.w);
    }
    return acc;
}

template <int P1, int P2, int P3>
__global__ __launch_bounds__(256) void speed_sampler_fused(
    const float* __restrict__ curIn,
    const float* __restrict__ indices,
    const float* __restrict__ value,
    const float* __restrict__ we1, const float* __restrict__ be1,
    const float* __restrict__ ww1, const float* __restrict__ bw1,
    const float* __restrict__ we2, const float* __restrict__ be2,
    const float* __restrict__ ww2, const float* __restrict__ bw2,
    const float* __restrict__ we3, const float* __restrict__ be3,
    const float* __restrict__ ww3, const float* __restrict__ bw3,
    const int* __restrict__ hsp_p, const int* __restrict__ wsp_p,
    float* __restrict__ out,
    int BFN, int BFHW)
{
    constexpr int S1 = WStride<P1>::v, S2 = WStride<P2>::v, S3 = WStride<P3>::v;
    __shared__ __align__(16) float sWb1[16 * S1];
    __shared__ __align__(16) float sWb2[16 * S2];
    __shared__ __align__(16) float sWb3[16 * S3];
    __shared__ float sB1[3 * P1], sB2[3 * P2], sB3[3 * P3];
    __shared__ __align__(16) float sPart[QPB * PREG];
    __shared__ __align__(16) float sLog[QPB * 16];

    const int tid = threadIdx.x;
    const int sl = tid & 15;
    const int qw = tid >> 4;
    const int q = blockIdx.x * QPB + qw;
    const int h = *hsp_p, w = *wsp_p;
    const int HW = h * w;
    const int BF = BFHW / HW;
    const int Nq = BFN / BF;
    const bool active = q < BFN;

    const float fh = (float)h, fw = (float)w;
    const float rwh = fw / fh, rhw = fh / fw;
    const float sc_x = 0.1f * rwh, sc_y = 0.1f * rhw;

    // ---- early loads + L1 prefetch of the base 2x2 neighborhood ----
    // Offsets are 0.1-scaled so all sampled points land in/near the base
    // coordinate's 2x2 patch; warming it here overlaps the DRAM latency with
    // weight staging + GEMM. Pure hint: mispredicted prefetches are harmless.
    float4 c4 = make_float4(0.f, 0.f, 0.f, 0.f);
    float base_x = -0.5f, base_y = -0.5f;
    const float* vbase = value + 4 * sl;
    if (active) {
        c4 = *reinterpret_cast<const float4*>(curIn + (size_t)q * 64 + 4 * sl);
        const float2 idx = *reinterpret_cast<const float2*>(indices + (size_t)q * 2);
        base_x = fmaf(idx.x, rwh, -0.5f);
        base_y = fmaf(idx.y, rhw, -0.5f);
        const int bf = q / Nq;
        vbase += (size_t)bf * HW * 64;

        const int px0 = (int)floorf(base_x), py0 = (int)floorf(base_y);
        const int pxc0 = min(max(px0, 0), w - 1);
        const int pxc1 = min(max(px0 + 1, 0), w - 1);
        const int pr0 = min(max(py0, 0), h - 1) * w;
        const int pr1 = min(max(py0 + 1, 0), h - 1) * w;
        asm volatile("prefetch.global.L1 [%0];" :: "l"(vbase + (pr0 + pxc0) * 64));
        asm volatile("prefetch.global.L1 [%0];" :: "l"(vbase + (pr0 + pxc1) * 64));
        asm volatile("prefetch.global.L1 [%0];" :: "l"(vbase + (pr1 + pxc0) * 64));
        asm volatile("prefetch.global.L1 [%0];" :: "l"(vbase + (pr1 + pxc1) * 64));
    }

    load_wb(sWb1, sB1, S1, we1, be1, ww1, bw1, P1, tid, blockDim.x);
    load_wb(sWb2, sB2, S2, we2, be2, ww2, bw2, P2, tid, blockDim.x);
    load_wb(sWb3, sB3, S3, we3, be3, ww3, bw3, P3, tid, blockDim.x);
    __syncthreads();

    float spx = 0.f, spy = 0.f;

    c4 = run_stage<P1>(c4, sl, qw, sWb1, sB1, sPart, sLog, spx, spy, base_x, base_y, sc_x, sc_y, h, w, vbase, active);
    c4 = run_stage<P2>(c4, sl, qw, sWb2, sB2, sPart, sLog, spx, spy, base_x, base_y, sc_x, sc_y, h, w, vbase, active);
    c4 = run_stage<P3>(c4, sl, qw, sWb3, sB3, sPart, sLog, spx, spy, base_x, base_y, sc_x, sc_y, h, w, vbase, active);

    if (active) {
        float* o = out + (size_t)q * 66 + 4 * sl;
        *reinterpret_cast<float2*>(o)     = make_float2(c4.x, c4.y);
        *reinterpret_cast<float2*>(o + 2) = make_float2(c4.z, c4.w);
        if (sl == 0) {
            out[(size_t)q * 66 + 64] = spx;
            out[(size_t)q * 66 + 65] = spy;
        }
    }
}

extern "C" void kernel_launch(void* const* d_in, const int* in_sizes, int n_in,
                              void* d_out, int out_size)
{
    const float* cur  = (const float*)d_in[0];
    const float* idxs = (const float*)d_in[1];
    const float* val  = (const float*)d_in[2];
    const int*   hsp  = (const int*)d_in[3];
    const int*   wsp  = (const int*)d_in[4];

    const int P1 = in_sizes[6] / 2;
    const int P2 = in_sizes[10] / 2;
    const int P3 = in_sizes[14] / 2;
    const int C  = in_sizes[5] / in_sizes[6];
    const int BFN  = in_sizes[0] / C;
    const int BFHW = in_sizes[2] / C;

    float* out = (float*)d_out;
    dim3 block(256);
    dim3 grid((BFN + QPB - 1) / QPB);

    if (P1 == 4 && P2 == 2 && P3 == 1) {
        speed_sampler_fused<4, 2, 1><<<grid, block>>>(
            cur, idxs, val,
            (const float*)d_in[5],  (const float*)d_in[6],
            (const float*)d_in[7],  (const float*)d_in[8],
            (const float*)d_in[9],  (const float*)d_in[10],
            (const float*)d_in[11], (const float*)d_in[12],
            (const float*)d_in[13], (const float*)d_in[14],
            (const float*)d_in[15], (const float*)d_in[16],
            hsp, wsp, out, BFN, BFHW);
    }
}